// round 2
// baseline (speedup 1.0000x reference)
#include <cuda_runtime.h>
#include <cstdint>

#define NN 4096
#define HID 256
#define NHEADS 8
#define HEADD 32
#define SCALE 0.17677669529663687f  // 1/sqrt(32)

// ---------------- scratch (static device globals; no allocation) ----------------
__device__ float    g_q[NHEADS][NN][HEADD];     // tf32-rounded q, head-major
__device__ float    g_v[NHEADS][NN][HEADD];     // tf32-rounded v, head-major
__device__ float    g_obuf[NN][HID];            // attn@v result, [n][h*32+d]
__device__ float    g_rowsum[NHEADS][NN];       // softmax denominators
__device__ unsigned g_mask[NN][NN / 32];        // Adj packed to bits

// ---------------- helpers ----------------
__device__ __forceinline__ float tf32r(float x) {
    unsigned u;
    asm("cvt.rna.tf32.f32 %0, %1;" : "=r"(u) : "f"(x));
    return __uint_as_float(u);
}

__device__ __forceinline__ void mma_tf32(float c[4],
                                         unsigned a0, unsigned a1, unsigned a2, unsigned a3,
                                         unsigned b0, unsigned b1) {
    asm volatile(
        "mma.sync.aligned.m16n8k8.row.col.f32.tf32.tf32.f32 "
        "{%0,%1,%2,%3},{%4,%5,%6,%7},{%8,%9},{%0,%1,%2,%3};\n"
        : "+f"(c[0]), "+f"(c[1]), "+f"(c[2]), "+f"(c[3])
        : "r"(a0), "r"(a1), "r"(a2), "r"(a3), "r"(b0), "r"(b1));
}

// ---------------- kernel 1: pack Adj -> bitmask (coalesced, ballot) ----------------
__global__ void pack_mask_kernel(const int* __restrict__ Adj) {
    int t = blockIdx.x * blockDim.x + threadIdx.x;  // over NN*NN
    int n = t >> 12;
    int m = t & (NN - 1);
    unsigned bit = (Adj[(size_t)t] != 0) ? 1u : 0u;
    unsigned word = __ballot_sync(0xffffffffu, bit);
    if ((m & 31) == 0) g_mask[n][m >> 5] = word;
}

// ---------------- kernel 2: projection GEMM  C[n][o] = X@W^T + b ----------------
// mode 0: X=x   -> g_q (tf32-rounded, head-scattered)
// mode 1: X=x   -> g_v (tf32-rounded, head-scattered)
// mode 2: X=g_obuf -> Out[n*HID+o] (plain fp32, final output projection)
__global__ void gemm_proj_kernel(const float* __restrict__ Xin,
                                 const float* __restrict__ W,
                                 const float* __restrict__ bias,
                                 float* __restrict__ Out, int mode) {
    __shared__ float xs[64][33];
    __shared__ float ws[64][33];
    const float* X = (mode == 2) ? &g_obuf[0][0] : Xin;
    int tx = threadIdx.x, ty = threadIdx.y;
    int tid = ty * 16 + tx;
    int m0 = blockIdx.x * 64, o0 = blockIdx.y * 64;
    float acc[4][4] = {};
    for (int kb = 0; kb < HID; kb += 32) {
#pragma unroll
        for (int i = 0; i < 2; i++) {
            int idx = tid + i * 256;          // 0..511 float4 slots
            int r = idx >> 3, c = (idx & 7) * 4;
            float4 xv = *(const float4*)&X[(size_t)(m0 + r) * HID + kb + c];
            xs[r][c] = xv.x; xs[r][c + 1] = xv.y; xs[r][c + 2] = xv.z; xs[r][c + 3] = xv.w;
            float4 wv = *(const float4*)&W[(size_t)(o0 + r) * HID + kb + c];
            ws[r][c] = wv.x; ws[r][c + 1] = wv.y; ws[r][c + 2] = wv.z; ws[r][c + 3] = wv.w;
        }
        __syncthreads();
#pragma unroll
        for (int k = 0; k < 32; k++) {
            float a[4], b[4];
#pragma unroll
            for (int i = 0; i < 4; i++) a[i] = xs[ty * 4 + i][k];
#pragma unroll
            for (int j = 0; j < 4; j++) b[j] = ws[tx * 4 + j][k];
#pragma unroll
            for (int i = 0; i < 4; i++)
#pragma unroll
                for (int j = 0; j < 4; j++) acc[i][j] += a[i] * b[j];
        }
        __syncthreads();
    }
#pragma unroll
    for (int i = 0; i < 4; i++) {
        int n = m0 + ty * 4 + i;
#pragma unroll
        for (int j = 0; j < 4; j++) {
            int o = o0 + tx * 4 + j;
            float v = acc[i][j] + bias[o];
            if (mode == 2) {
                Out[(size_t)n * HID + o] = v;
            } else {
                float* dst = (mode == 0) ? &g_q[0][0][0] : &g_v[0][0][0];
                dst[((size_t)(o >> 5) * NN + n) * HEADD + (o & 31)] = tf32r(v);
            }
        }
    }
}

// ---------------- attention passes ----------------
// Pass A (PB=false): compute rowsums of exp(masked scores).
// Pass B (PB=true):  recompute scores, normalize, write attn, accumulate O = P@V.
// CTA: 256 threads (8 warps), 128 query rows per CTA, loop over 32 key tiles of 128.
constexpr int QS_ELEMS = 128 * 36;
constexpr int VS_ELEMS = 128 * 36;
constexpr int PS_ELEMS = 128 * 132;
constexpr int MS_WORDS = 128 * 4;
constexpr int SMEM_A_BYTES = (QS_ELEMS + VS_ELEMS + MS_WORDS) * 4;
constexpr int SMEM_B_BYTES = (QS_ELEMS + VS_ELEMS + PS_ELEMS + MS_WORDS) * 4;

template <bool PB>
__global__ __launch_bounds__(256, 2) void attn_pass_kernel(float* __restrict__ attn_out) {
    extern __shared__ float smem[];
    float* qs = smem;                    // [128][36]
    float* vs = qs + QS_ELEMS;           // [128][36]
    float* ps = PB ? (vs + VS_ELEMS) : nullptr;  // [128][132]
    unsigned* ms = (unsigned*)(PB ? (ps + PS_ELEMS) : (vs + VS_ELEMS));  // [128][4]

    const int head = blockIdx.y;
    const int n0 = blockIdx.x * 128;
    const int tid = threadIdx.x;
    const int warp = tid >> 5, lane = tid & 31;
    const int g = lane >> 2, tq = lane & 3;
    const int r0 = 16 * warp + g;   // local rows owned by this thread
    const int r1 = r0 + 8;

    // load Q block (128 x 32)
    {
        const float* qsrc = &g_q[head][n0][0];
#pragma unroll
        for (int i = 0; i < 4; i++) {
            int idx = tid + i * 256;
            int r = idx >> 3, c = (idx & 7) * 4;
            *(float4*)&qs[r * 36 + c] = *(const float4*)&qsrc[r * HEADD + c];
        }
    }

    float oacc[4][4];
    float rs0 = 0.f, rs1 = 0.f;
    float inv0 = 0.f, inv1 = 0.f;
    if (PB) {
#pragma unroll
        for (int i = 0; i < 4; i++)
#pragma unroll
            for (int j = 0; j < 4; j++) oacc[i][j] = 0.f;
        inv0 = 1.0f / g_rowsum[head][n0 + r0];
        inv1 = 1.0f / g_rowsum[head][n0 + r1];
    }

    for (int tile = 0; tile < 32; tile++) {
        __syncthreads();
        // load V tile (128 x 32) and mask tile (128 x 4 words)
        {
            const float* vsrc = &g_v[head][tile * 128][0];
#pragma unroll
            for (int i = 0; i < 4; i++) {
                int idx = tid + i * 256;
                int r = idx >> 3, c = (idx & 7) * 4;
                *(float4*)&vs[r * 36 + c] = *(const float4*)&vsrc[r * HEADD + c];
            }
#pragma unroll
            for (int i = 0; i < 2; i++) {
                int idx = tid + i * 256;
                ms[idx] = g_mask[n0 + (idx >> 2)][tile * 4 + (idx & 3)];
            }
        }
        __syncthreads();

        // ---- MMA 1: S = Q @ V^T (128x128, k=32) ----
        float c[16][4];
#pragma unroll
        for (int s = 0; s < 16; s++)
#pragma unroll
            for (int j = 0; j < 4; j++) c[s][j] = 0.f;
#pragma unroll
        for (int kc = 0; kc < 4; kc++) {
            unsigned a0 = __float_as_uint(qs[r0 * 36 + kc * 8 + tq]);
            unsigned a1 = __float_as_uint(qs[r1 * 36 + kc * 8 + tq]);
            unsigned a2 = __float_as_uint(qs[r0 * 36 + kc * 8 + tq + 4]);
            unsigned a3 = __float_as_uint(qs[r1 * 36 + kc * 8 + tq + 4]);
#pragma unroll
            for (int sub = 0; sub < 16; sub++) {
                unsigned b0 = __float_as_uint(vs[(sub * 8 + g) * 36 + kc * 8 + tq]);
                unsigned b1 = __float_as_uint(vs[(sub * 8 + g) * 36 + kc * 8 + tq + 4]);
                mma_tf32(c[sub], a0, a1, a2, a3, b0, b1);
            }
        }

        // ---- mask + exp (+ normalize/store for pass B) ----
#pragma unroll
        for (int sub = 0; sub < 16; sub++) {
            int colb = sub * 8 + 2 * tq;
            unsigned w0 = ms[r0 * 4 + (sub >> 2)];
            unsigned w1 = ms[r1 * 4 + (sub >> 2)];
            int sh = colb & 31;
            float p00 = ((w0 >> sh) & 1u) ? __expf(c[sub][0] * SCALE) : 0.f;
            float p01 = ((w0 >> sh) & 2u) ? __expf(c[sub][1] * SCALE) : 0.f;
            float p10 = ((w1 >> sh) & 1u) ? __expf(c[sub][2] * SCALE) : 0.f;
            float p11 = ((w1 >> sh) & 2u) ? __expf(c[sub][3] * SCALE) : 0.f;
            if (PB) {
                p00 *= inv0; p01 *= inv0; p10 *= inv1; p11 *= inv1;
                size_t b0a = ((size_t)(head * NN + (n0 + r0))) * NN + tile * 128 + colb;
                size_t b1a = ((size_t)(head * NN + (n0 + r1))) * NN + tile * 128 + colb;
                *(float2*)&attn_out[b0a] = make_float2(p00, p01);
                *(float2*)&attn_out[b1a] = make_float2(p10, p11);
                *(float2*)&ps[r0 * 132 + colb] = make_float2(tf32r(p00), tf32r(p01));
                *(float2*)&ps[r1 * 132 + colb] = make_float2(tf32r(p10), tf32r(p11));
            } else {
                rs0 += p00 + p01;
                rs1 += p10 + p11;
            }
        }

        // ---- MMA 2 (pass B): O += P @ V (128x32, k=128) ----
        if (PB) {
            __syncwarp();  // P rows are warp-private; make stores visible to quad
#pragma unroll
            for (int kc = 0; kc < 16; kc++) {
                unsigned a0 = __float_as_uint(ps[r0 * 132 + kc * 8 + tq]);
                unsigned a1 = __float_as_uint(ps[r1 * 132 + kc * 8 + tq]);
                unsigned a2 = __float_as_uint(ps[r0 * 132 + kc * 8 + tq + 4]);
                unsigned a3 = __float_as_uint(ps[r1 * 132 + kc * 8 + tq + 4]);
#pragma unroll
                for (int ds = 0; ds < 4; ds++) {
                    unsigned b0 = __float_as_uint(vs[(kc * 8 + tq) * 36 + ds * 8 + g]);
                    unsigned b1 = __float_as_uint(vs[(kc * 8 + tq + 4) * 36 + ds * 8 + g]);
                    mma_tf32(oacc[ds], a0, a1, a2, a3, b0, b1);
                }
            }
        }
    }

    if (PB) {
#pragma unroll
        for (int ds = 0; ds < 4; ds++) {
            int col = head * 32 + ds * 8 + 2 * tq;
            *(float2*)&g_obuf[n0 + r0][col] = make_float2(oacc[ds][0], oacc[ds][1]);
            *(float2*)&g_obuf[n0 + r1][col] = make_float2(oacc[ds][2], oacc[ds][3]);
        }
    } else {
        rs0 += __shfl_xor_sync(0xffffffffu, rs0, 1);
        rs0 += __shfl_xor_sync(0xffffffffu, rs0, 2);
        rs1 += __shfl_xor_sync(0xffffffffu, rs1, 1);
        rs1 += __shfl_xor_sync(0xffffffffu, rs1, 2);
        if (tq == 0) {
            g_rowsum[head][n0 + r0] = rs0;
            g_rowsum[head][n0 + r1] = rs1;
        }
    }
}

// ---------------- launch ----------------
extern "C" void kernel_launch(void* const* d_in, const int* in_sizes, int n_in,
                              void* d_out, int out_size) {
    (void)in_sizes; (void)n_in; (void)out_size;
    const float* x  = (const float*)d_in[0];
    const int*   Adj = (const int*)d_in[1];
    const float* wq = (const float*)d_in[2];
    const float* bq = (const float*)d_in[3];
    // wk (d_in[4], d_in[5]) unused: reference has the q@v^T bug
    const float* wv = (const float*)d_in[6];
    const float* bv = (const float*)d_in[7];
    const float* wo = (const float*)d_in[8];
    const float* bo = (const float*)d_in[9];
    float* out = (float*)d_out;
    float* attn = out + (size_t)NN * HID;

    cudaFuncSetAttribute(attn_pass_kernel<false>,
                         cudaFuncAttributeMaxDynamicSharedMemorySize, SMEM_A_BYTES);
    cudaFuncSetAttribute(attn_pass_kernel<true>,
                         cudaFuncAttributeMaxDynamicSharedMemorySize, SMEM_B_BYTES);

    pack_mask_kernel<<<(NN * NN) / 256, 256>>>(Adj);

    dim3 pg(NN / 64, HID / 64);
    dim3 pt(16, 16);
    gemm_proj_kernel<<<pg, pt>>>(x, wq, bq, nullptr, 0);
    gemm_proj_kernel<<<pg, pt>>>(x, wv, bv, nullptr, 1);

    attn_pass_kernel<false><<<dim3(32, 8), 256, SMEM_A_BYTES>>>(attn);
    attn_pass_kernel<true><<<dim3(32, 8), 256, SMEM_B_BYTES>>>(attn);

    gemm_proj_kernel<<<pg, pt>>>(nullptr, wo, bo, out, 2);
}

// round 5
// speedup vs baseline: 1.2268x; 1.2268x over previous
#include <cuda_runtime.h>
#include <cuda_fp16.h>
#include <cstdint>

#define NN 4096
#define HID 256
#define NHEADS 8
#define HEADD 32
#define SCALE 0.17677669529663687f  // 1/sqrt(32)

// ---------------- scratch (static device globals; no allocation) ----------------
__device__ float    g_q[NHEADS][NN][HEADD];     // tf32-rounded q, head-major
__device__ float    g_v[NHEADS][NN][HEADD];     // tf32-rounded v, head-major
__device__ float    g_obuf[NN][HID];            // normalized attn@v, [n][h*32+d]
__device__ float    g_inv[NHEADS][NN];          // 1/rowsum
__device__ unsigned g_mask[NN][NN / 32];        // Adj packed to bits
__device__ __half   g_E[NHEADS][NN][NN];        // unnormalized masked exp(scores), fp16

// ---------------- helpers ----------------
__device__ __forceinline__ float tf32r(float x) {
    unsigned u;
    asm("cvt.rna.tf32.f32 %0, %1;" : "=r"(u) : "f"(x));
    return __uint_as_float(u);
}

__device__ __forceinline__ void mma_tf32(float c[4],
                                         unsigned a0, unsigned a1, unsigned a2, unsigned a3,
                                         unsigned b0, unsigned b1) {
    asm volatile(
        "mma.sync.aligned.m16n8k8.row.col.f32.tf32.tf32.f32 "
        "{%0,%1,%2,%3},{%4,%5,%6,%7},{%8,%9},{%0,%1,%2,%3};\n"
        : "+f"(c[0]), "+f"(c[1]), "+f"(c[2]), "+f"(c[3])
        : "r"(a0), "r"(a1), "r"(a2), "r"(a3), "r"(b0), "r"(b1));
}

__device__ __forceinline__ void mma_f16(float c[4],
                                        unsigned a0, unsigned a1, unsigned a2, unsigned a3,
                                        unsigned b0, unsigned b1) {
    asm volatile(
        "mma.sync.aligned.m16n8k16.row.col.f32.f16.f16.f32 "
        "{%0,%1,%2,%3},{%4,%5,%6,%7},{%8,%9},{%0,%1,%2,%3};\n"
        : "+f"(c[0]), "+f"(c[1]), "+f"(c[2]), "+f"(c[3])
        : "r"(a0), "r"(a1), "r"(a2), "r"(a3), "r"(b0), "r"(b1));
}

__device__ __forceinline__ unsigned h2u(__half2 h) {
    return *reinterpret_cast<unsigned*>(&h);
}

// ---------------- kernel 1: pack Adj -> bitmask ----------------
__global__ void pack_mask_kernel(const int* __restrict__ Adj) {
    int t = blockIdx.x * blockDim.x + threadIdx.x;
    int n = t >> 12;
    int m = t & (NN - 1);
    unsigned bit = (Adj[(size_t)t] != 0) ? 1u : 0u;
    unsigned word = __ballot_sync(0xffffffffu, bit);
    if ((m & 31) == 0) g_mask[n][m >> 5] = word;
}

// ---------------- projection GEMMs (SIMT, proven) ----------------
__global__ void gemm_qv_kernel(const float* __restrict__ x,
                               const float* __restrict__ wq, const float* __restrict__ bq,
                               const float* __restrict__ wv, const float* __restrict__ bv) {
    __shared__ float xs[64][33];
    __shared__ float ws[64][33];
    const float* W  = blockIdx.z ? wv : wq;
    const float* Bb = blockIdx.z ? bv : bq;
    float* dst = blockIdx.z ? &g_v[0][0][0] : &g_q[0][0][0];
    int tx = threadIdx.x, ty = threadIdx.y;
    int tid = ty * 16 + tx;
    int m0 = blockIdx.x * 64, o0 = blockIdx.y * 64;
    float acc[4][4] = {};
    for (int kb = 0; kb < HID; kb += 32) {
#pragma unroll
        for (int i = 0; i < 2; i++) {
            int idx = tid + i * 256;
            int r = idx >> 3, c = (idx & 7) * 4;
            float4 xv = *(const float4*)&x[(size_t)(m0 + r) * HID + kb + c];
            xs[r][c] = xv.x; xs[r][c + 1] = xv.y; xs[r][c + 2] = xv.z; xs[r][c + 3] = xv.w;
            float4 wv4 = *(const float4*)&W[(size_t)(o0 + r) * HID + kb + c];
            ws[r][c] = wv4.x; ws[r][c + 1] = wv4.y; ws[r][c + 2] = wv4.z; ws[r][c + 3] = wv4.w;
        }
        __syncthreads();
#pragma unroll
        for (int k = 0; k < 32; k++) {
            float a[4], b[4];
#pragma unroll
            for (int i = 0; i < 4; i++) a[i] = xs[ty * 4 + i][k];
#pragma unroll
            for (int j = 0; j < 4; j++) b[j] = ws[tx * 4 + j][k];
#pragma unroll
            for (int i = 0; i < 4; i++)
#pragma unroll
                for (int j = 0; j < 4; j++) acc[i][j] += a[i] * b[j];
        }
        __syncthreads();
    }
#pragma unroll
    for (int i = 0; i < 4; i++) {
        int n = m0 + ty * 4 + i;
#pragma unroll
        for (int j = 0; j < 4; j++) {
            int o = o0 + tx * 4 + j;
            float v = acc[i][j] + Bb[o];
            dst[((size_t)(o >> 5) * NN + n) * HEADD + (o & 31)] = tf32r(v);
        }
    }
}

__global__ void gemm_o_kernel(const float* __restrict__ W,
                              const float* __restrict__ bias, float* __restrict__ Out) {
    __shared__ float xs[64][33];
    __shared__ float ws[64][33];
    const float* X = &g_obuf[0][0];
    int tx = threadIdx.x, ty = threadIdx.y;
    int tid = ty * 16 + tx;
    int m0 = blockIdx.x * 64, o0 = blockIdx.y * 64;
    float acc[4][4] = {};
    for (int kb = 0; kb < HID; kb += 32) {
#pragma unroll
        for (int i = 0; i < 2; i++) {
            int idx = tid + i * 256;
            int r = idx >> 3, c = (idx & 7) * 4;
            float4 xv = *(const float4*)&X[(size_t)(m0 + r) * HID + kb + c];
            xs[r][c] = xv.x; xs[r][c + 1] = xv.y; xs[r][c + 2] = xv.z; xs[r][c + 3] = xv.w;
            float4 wv4 = *(const float4*)&W[(size_t)(o0 + r) * HID + kb + c];
            ws[r][c] = wv4.x; ws[r][c + 1] = wv4.y; ws[r][c + 2] = wv4.z; ws[r][c + 3] = wv4.w;
        }
        __syncthreads();
#pragma unroll
        for (int k = 0; k < 32; k++) {
            float a[4], b[4];
#pragma unroll
            for (int i = 0; i < 4; i++) a[i] = xs[ty * 4 + i][k];
#pragma unroll
            for (int j = 0; j < 4; j++) b[j] = ws[tx * 4 + j][k];
#pragma unroll
            for (int i = 0; i < 4; i++)
#pragma unroll
                for (int j = 0; j < 4; j++) acc[i][j] += a[i] * b[j];
        }
        __syncthreads();
    }
#pragma unroll
    for (int i = 0; i < 4; i++) {
        int n = m0 + ty * 4 + i;
#pragma unroll
        for (int j = 0; j < 4; j++) {
            int o = o0 + tx * 4 + j;
            Out[(size_t)n * HID + o] = acc[i][j] + bias[o];
        }
    }
}

// ---------------- pass 1: S=Q@V^T (tf32) -> E=exp fp16 (store) -> O=E@V (f16 mma) ----------------
// CTA: 256 threads (8 warps). Warp w owns rows 16w..16w+15 across all 128 tile cols.
// C-frag of tf32 m16n8k8 (cols 2tq,2tq+1) IS the f16 m16n8k16 A-frag k-pattern -> zero-copy MMA2.
__global__ __launch_bounds__(256, 2) void attn_pass1_kernel() {
    __shared__ float    qs[128][36];
    __shared__ float    vs[128][36];
    __shared__ __half   vsT[32][136];   // pad 136: b-load bank = 4g+tq, conflict-free
    __shared__ unsigned ms[128][4];

    const int head = blockIdx.y;
    const int n0 = blockIdx.x * 128;
    const int tid = threadIdx.x;
    const int warp = tid >> 5, lane = tid & 31;
    const int g = lane >> 2, tq = lane & 3;
    const int r0 = 16 * warp + g;
    const int r1 = r0 + 8;

    // load Q tile (once)
    {
        const float* qsrc = &g_q[head][n0][0];
#pragma unroll
        for (int i = 0; i < 4; i++) {
            int idx = tid + i * 256;
            int r = idx >> 3, c = (idx & 7) * 4;
            *(float4*)&qs[r][c] = *(const float4*)&qsrc[r * HEADD + c];
        }
    }

    float oacc[4][4];
#pragma unroll
    for (int i = 0; i < 4; i++)
#pragma unroll
        for (int j = 0; j < 4; j++) oacc[i][j] = 0.f;
    float rs0 = 0.f, rs1 = 0.f;

    for (int tile = 0; tile < 32; tile++) {
        __syncthreads();
        // load V tile: fp32 -> vs (for MMA1 B) and fp16 transposed -> vsT (for MMA2 B)
        {
            const float* vsrc = &g_v[head][tile * 128][0];
#pragma unroll
            for (int i = 0; i < 4; i++) {
                int idx = tid + i * 256;
                int r = idx >> 3, c = (idx & 7) * 4;
                float4 vv = *(const float4*)&vsrc[r * HEADD + c];
                *(float4*)&vs[r][c] = vv;
                vsT[c + 0][r] = __float2half_rn(vv.x);
                vsT[c + 1][r] = __float2half_rn(vv.y);
                vsT[c + 2][r] = __float2half_rn(vv.z);
                vsT[c + 3][r] = __float2half_rn(vv.w);
            }
#pragma unroll
            for (int i = 0; i < 2; i++) {
                int idx = tid + i * 256;
                ms[idx >> 2][idx & 3] = g_mask[n0 + (idx >> 2)][tile * 4 + (idx & 3)];
            }
        }
        __syncthreads();

        // ---- MMA1: S = Q @ V^T (tf32, 128x128, k=32) ----
        float c[16][4];
#pragma unroll
        for (int s = 0; s < 16; s++)
#pragma unroll
            for (int j = 0; j < 4; j++) c[s][j] = 0.f;
#pragma unroll
        for (int kc = 0; kc < 4; kc++) {
            unsigned a0 = __float_as_uint(qs[r0][kc * 8 + tq]);
            unsigned a1 = __float_as_uint(qs[r1][kc * 8 + tq]);
            unsigned a2 = __float_as_uint(qs[r0][kc * 8 + tq + 4]);
            unsigned a3 = __float_as_uint(qs[r1][kc * 8 + tq + 4]);
#pragma unroll
            for (int sub = 0; sub < 16; sub++) {
                unsigned b0 = __float_as_uint(vs[sub * 8 + g][kc * 8 + tq]);
                unsigned b1 = __float_as_uint(vs[sub * 8 + g][kc * 8 + tq + 4]);
                mma_tf32(c[sub], a0, a1, a2, a3, b0, b1);
            }
        }

        // ---- epilogue: mask + exp -> rowsum, STG E (fp16), keep f16 A-frags in regs ----
        unsigned ah0[16], ah1[16];
        __half* e0base = &g_E[head][n0 + r0][tile * 128 + 2 * tq];
        __half* e1base = &g_E[head][n0 + r1][tile * 128 + 2 * tq];
#pragma unroll
        for (int sub = 0; sub < 16; sub++) {
            int colb = sub * 8 + 2 * tq;
            unsigned w0 = ms[r0][sub >> 2];
            unsigned w1 = ms[r1][sub >> 2];
            int sh = colb & 31;
            float e0 = ((w0 >> sh) & 1u) ? __expf(c[sub][0] * SCALE) : 0.f;
            float e1 = ((w0 >> sh) & 2u) ? __expf(c[sub][1] * SCALE) : 0.f;
            float e2 = ((w1 >> sh) & 1u) ? __expf(c[sub][2] * SCALE) : 0.f;
            float e3 = ((w1 >> sh) & 2u) ? __expf(c[sub][3] * SCALE) : 0.f;
            rs0 += e0 + e1;
            rs1 += e2 + e3;
            __half2 h01 = __floats2half2_rn(e0, e1);   // lo = lower k index
            __half2 h23 = __floats2half2_rn(e2, e3);
            ah0[sub] = h2u(h01);
            ah1[sub] = h2u(h23);
            *(unsigned*)(e0base + sub * 8) = ah0[sub];
            *(unsigned*)(e1base + sub * 8) = ah1[sub];
        }

        // ---- MMA2: O += E @ V (f16 m16n8k16, A from regs, B from vsT) ----
#pragma unroll
        for (int kc = 0; kc < 8; kc++) {
            unsigned a0 = ah0[2 * kc];
            unsigned a1 = ah1[2 * kc];
            unsigned a2 = ah0[2 * kc + 1];
            unsigned a3 = ah1[2 * kc + 1];
#pragma unroll
            for (int ds = 0; ds < 4; ds++) {
                unsigned b0 = *(const unsigned*)&vsT[ds * 8 + g][16 * kc + 2 * tq];
                unsigned b1 = *(const unsigned*)&vsT[ds * 8 + g][16 * kc + 2 * tq + 8];
                mma_f16(oacc[ds], a0, a1, a2, a3, b0, b1);
            }
        }
    }

    // rowsum: quad (tq) butterfly -> every lane has full row sum; normalize O in regs
    rs0 += __shfl_xor_sync(0xffffffffu, rs0, 1);
    rs0 += __shfl_xor_sync(0xffffffffu, rs0, 2);
    rs1 += __shfl_xor_sync(0xffffffffu, rs1, 1);
    rs1 += __shfl_xor_sync(0xffffffffu, rs1, 2);
    float inv0 = 1.0f / rs0;
    float inv1 = 1.0f / rs1;
    if (tq == 0) {
        g_inv[head][n0 + r0] = inv0;
        g_inv[head][n0 + r1] = inv1;
    }
#pragma unroll
    for (int ds = 0; ds < 4; ds++) {
        int col = head * 32 + ds * 8 + 2 * tq;
        *(float2*)&g_obuf[n0 + r0][col] = make_float2(oacc[ds][0] * inv0, oacc[ds][1] * inv0);
        *(float2*)&g_obuf[n0 + r1][col] = make_float2(oacc[ds][2] * inv1, oacc[ds][3] * inv1);
    }
}

// ---------------- pass 2: attn = E * inv (pure streaming) ----------------
__global__ __launch_bounds__(256) void scale_kernel(float* __restrict__ attn) {
    int bid = blockIdx.x;           // 0 .. 8*4096-1  (one row per block)
    int h = bid >> 12;
    int n = bid & (NN - 1);
    float inv = g_inv[h][n];
    const __half2* E = (const __half2*)&g_E[h][n][0];   // 2048 half2
    float2* dst = (float2*)&attn[((size_t)(h * NN + n)) * NN];
#pragma unroll 4
    for (int i = threadIdx.x; i < NN / 2; i += 256) {
        float2 f = __half22float2(E[i]);
        dst[i] = make_float2(f.x * inv, f.y * inv);
    }
}

// ---------------- launch ----------------
extern "C" void kernel_launch(void* const* d_in, const int* in_sizes, int n_in,
                              void* d_out, int out_size) {
    (void)in_sizes; (void)n_in; (void)out_size;
    const float* x   = (const float*)d_in[0];
    const int*   Adj = (const int*)d_in[1];
    const float* wq  = (const float*)d_in[2];
    const float* bq  = (const float*)d_in[3];
    // wk (d_in[4], d_in[5]) unused: reference has the q@v^T bug
    const float* wv  = (const float*)d_in[6];
    const float* bv  = (const float*)d_in[7];
    const float* wo  = (const float*)d_in[8];
    const float* bo  = (const float*)d_in[9];
    float* out  = (float*)d_out;
    float* attn = out + (size_t)NN * HID;

    pack_mask_kernel<<<(NN * NN) / 256, 256>>>(Adj);

    dim3 pt(16, 16);
    gemm_qv_kernel<<<dim3(NN / 64, HID / 64, 2), pt>>>(x, wq, bq, wv, bv);

    attn_pass1_kernel<<<dim3(32, 8), 256>>>();
    scale_kernel<<<NHEADS * NN, 256>>>(attn);

    gemm_o_kernel<<<dim3(NN / 64, HID / 64), pt>>>(wo, bo, out);
}

// round 7
// speedup vs baseline: 1.3714x; 1.1178x over previous
#include <cuda_runtime.h>
#include <cuda_fp16.h>
#include <cstdint>

#define NN 4096
#define HID 256
#define NHEADS 8
#define HEADD 32
#define SCALE 0.17677669529663687f  // 1/sqrt(32)

// ---------------- scratch (static device globals; no allocation) ----------------
__device__ __half   g_q[NHEADS][NN][HEADD];     // fp16 q, head-major
__device__ __half   g_v[NHEADS][NN][HEADD];     // fp16 v, head-major
__device__ float    g_obuf[NN][HID];            // normalized attn@v, [n][h*32+d]
__device__ float    g_inv[NHEADS][NN];          // 1/rowsum
__device__ unsigned g_mask[NN][NN / 32];        // Adj packed to bits
__device__ __half   g_E[NHEADS][NN][NN];        // unnormalized masked exp(scores), fp16

// ---------------- helpers ----------------
__device__ __forceinline__ uint32_t smem_u32(const void* p) {
    uint32_t a;
    asm("{ .reg .u64 t; cvta.to.shared.u64 t, %1; cvt.u32.u64 %0, t; }" : "=r"(a) : "l"(p));
    return a;
}

__device__ __forceinline__ void mma_f16(float c[4],
                                        unsigned a0, unsigned a1, unsigned a2, unsigned a3,
                                        unsigned b0, unsigned b1) {
    asm volatile(
        "mma.sync.aligned.m16n8k16.row.col.f32.f16.f16.f32 "
        "{%0,%1,%2,%3},{%4,%5,%6,%7},{%8,%9},{%0,%1,%2,%3};\n"
        : "+f"(c[0]), "+f"(c[1]), "+f"(c[2]), "+f"(c[3])
        : "r"(a0), "r"(a1), "r"(a2), "r"(a3), "r"(b0), "r"(b1));
}

#define LDSM_X4(d, addr) \
    asm volatile("ldmatrix.sync.aligned.m8n8.x4.shared.b16 {%0,%1,%2,%3}, [%4];" \
        : "=r"((d)[0]), "=r"((d)[1]), "=r"((d)[2]), "=r"((d)[3]) : "r"(addr))

#define LDSM_X4T(d, addr) \
    asm volatile("ldmatrix.sync.aligned.m8n8.x4.trans.shared.b16 {%0,%1,%2,%3}, [%4];" \
        : "=r"((d)[0]), "=r"((d)[1]), "=r"((d)[2]), "=r"((d)[3]) : "r"(addr))

__device__ __forceinline__ unsigned h2u(__half2 h) {
    return *reinterpret_cast<unsigned*>(&h);
}

// ---------------- kernel 1: pack Adj -> bitmask ----------------
__global__ void pack_mask_kernel(const int* __restrict__ Adj) {
    int t = blockIdx.x * blockDim.x + threadIdx.x;
    int n = t >> 12;
    int m = t & (NN - 1);
    unsigned bit = (Adj[(size_t)t] != 0) ? 1u : 0u;
    unsigned word = __ballot_sync(0xffffffffu, bit);
    if ((m & 31) == 0) g_mask[n][m >> 5] = word;
}

// ---------------- projection GEMMs ----------------
__global__ void gemm_qv_kernel(const float* __restrict__ x,
                               const float* __restrict__ wq, const float* __restrict__ bq,
                               const float* __restrict__ wv, const float* __restrict__ bv) {
    __shared__ float xs[64][33];
    __shared__ float ws[64][33];
    const float* W  = blockIdx.z ? wv : wq;
    const float* Bb = blockIdx.z ? bv : bq;
    __half* dst = blockIdx.z ? &g_v[0][0][0] : &g_q[0][0][0];
    int tx = threadIdx.x, ty = threadIdx.y;
    int tid = ty * 16 + tx;
    int m0 = blockIdx.x * 64, o0 = blockIdx.y * 64;
    float acc[4][4] = {};
    for (int kb = 0; kb < HID; kb += 32) {
#pragma unroll
        for (int i = 0; i < 2; i++) {
            int idx = tid + i * 256;
            int r = idx >> 3, c = (idx & 7) * 4;
            float4 xv = *(const float4*)&x[(size_t)(m0 + r) * HID + kb + c];
            xs[r][c] = xv.x; xs[r][c + 1] = xv.y; xs[r][c + 2] = xv.z; xs[r][c + 3] = xv.w;
            float4 wv4 = *(const float4*)&W[(size_t)(o0 + r) * HID + kb + c];
            ws[r][c] = wv4.x; ws[r][c + 1] = wv4.y; ws[r][c + 2] = wv4.z; ws[r][c + 3] = wv4.w;
        }
        __syncthreads();
#pragma unroll
        for (int k = 0; k < 32; k++) {
            float a[4], b[4];
#pragma unroll
            for (int i = 0; i < 4; i++) a[i] = xs[ty * 4 + i][k];
#pragma unroll
            for (int j = 0; j < 4; j++) b[j] = ws[tx * 4 + j][k];
#pragma unroll
            for (int i = 0; i < 4; i++)
#pragma unroll
                for (int j = 0; j < 4; j++) acc[i][j] += a[i] * b[j];
        }
        __syncthreads();
    }
#pragma unroll
    for (int i = 0; i < 4; i++) {
        int n = m0 + ty * 4 + i;
#pragma unroll
        for (int jp = 0; jp < 2; jp++) {
            int o = o0 + tx * 4 + jp * 2;
            __half2 h = __floats2half2_rn(acc[i][jp * 2] + Bb[o], acc[i][jp * 2 + 1] + Bb[o + 1]);
            *(__half2*)&dst[((size_t)(o >> 5) * NN + n) * HEADD + (o & 31)] = h;
        }
    }
}

__global__ void gemm_o_kernel(const float* __restrict__ W,
                              const float* __restrict__ bias, float* __restrict__ Out) {
    __shared__ float xs[64][33];
    __shared__ float ws[64][33];
    const float* X = &g_obuf[0][0];
    int tx = threadIdx.x, ty = threadIdx.y;
    int tid = ty * 16 + tx;
    int m0 = blockIdx.x * 64, o0 = blockIdx.y * 64;
    float acc[4][4] = {};
    for (int kb = 0; kb < HID; kb += 32) {
#pragma unroll
        for (int i = 0; i < 2; i++) {
            int idx = tid + i * 256;
            int r = idx >> 3, c = (idx & 7) * 4;
            float4 xv = *(const float4*)&X[(size_t)(m0 + r) * HID + kb + c];
            xs[r][c] = xv.x; xs[r][c + 1] = xv.y; xs[r][c + 2] = xv.z; xs[r][c + 3] = xv.w;
            float4 wv4 = *(const float4*)&W[(size_t)(o0 + r) * HID + kb + c];
            ws[r][c] = wv4.x; ws[r][c + 1] = wv4.y; ws[r][c + 2] = wv4.z; ws[r][c + 3] = wv4.w;
        }
        __syncthreads();
#pragma unroll
        for (int k = 0; k < 32; k++) {
            float a[4], b[4];
#pragma unroll
            for (int i = 0; i < 4; i++) a[i] = xs[ty * 4 + i][k];
#pragma unroll
            for (int j = 0; j < 4; j++) b[j] = ws[tx * 4 + j][k];
#pragma unroll
            for (int i = 0; i < 4; i++)
#pragma unroll
                for (int j = 0; j < 4; j++) acc[i][j] += a[i] * b[j];
        }
        __syncthreads();
    }
#pragma unroll
    for (int i = 0; i < 4; i++) {
        int n = m0 + ty * 4 + i;
#pragma unroll
        for (int j = 0; j < 4; j++) {
            int o = o0 + tx * 4 + j;
            Out[(size_t)n * HID + o] = acc[i][j] + bias[o];
        }
    }
}

// ---------------- pass 1: S=Q@V^T (f16 mma) -> E fp16 (smem-staged store) -> O=E@V ----------------
// CTA: 256 threads (8 warps). Warp w owns rows 16w..16w+15.
// Fragments fed by ldmatrix; MMA2 B via ldmatrix.trans on the same K-major V tile.
constexpr int QS_OFF = 0;        // [128][40] half  (10240 B)
constexpr int VS_OFF = 10240;    // [128][40] half  (10240 B)
constexpr int ES_OFF = 20480;    // [128][136] half (34816 B)
constexpr int MS_OFF = 55296;    // [128][4] unsigned (2048 B)
constexpr int SMEM_P1 = 57344;

__global__ __launch_bounds__(256, 2) void attn_pass1_kernel() {
    extern __shared__ char sm[];
    __half* qs = (__half*)(sm + QS_OFF);        // row stride 40
    __half* vs = (__half*)(sm + VS_OFF);        // row stride 40
    __half* es = (__half*)(sm + ES_OFF);        // row stride 136
    unsigned* msp = (unsigned*)(sm + MS_OFF);
    const uint32_t sb = smem_u32(sm);

    const int head = blockIdx.y;
    const int n0 = blockIdx.x * 128;
    const int tid = threadIdx.x;
    const int warp = tid >> 5, lane = tid & 31;
    const int g = lane >> 2, tq = lane & 3;
    const int li = lane >> 3, lj = lane & 7;
    const int r0 = 16 * warp + g;
    const int r1 = r0 + 8;

    // ldmatrix lane-address invariants (bytes)
    const uint32_t qa_base = sb + QS_OFF + (16 * warp + (li & 1) * 8 + lj) * 80 + ((li >> 1) * 8) * 2;
    const uint32_t vb_base = sb + VS_OFF + ((li >> 1) * 8 + lj) * 80 + ((li & 1) * 8) * 2;
    const uint32_t vt_base = sb + VS_OFF + ((li & 1) * 8 + lj) * 80 + ((li >> 1) * 8) * 2;

    // load Q tile (128x32 fp16) once
    {
        const __half* qsrc = &g_q[head][n0][0];
#pragma unroll
        for (int i = 0; i < 2; i++) {
            int idx = tid + i * 256;
            int r = idx >> 2, c8 = (idx & 3) * 8;
            *(uint4*)&qs[r * 40 + c8] = *(const uint4*)&qsrc[r * HEADD + c8];
        }
    }

    float oacc[4][4];
#pragma unroll
    for (int i = 0; i < 4; i++)
#pragma unroll
        for (int j = 0; j < 4; j++) oacc[i][j] = 0.f;
    float rs0 = 0.f, rs1 = 0.f;

    for (int tile = 0; tile < 32; tile++) {
        __syncthreads();
        // load V tile (128x32 fp16) + mask tile
        {
            const __half* vsrc = &g_v[head][tile * 128][0];
#pragma unroll
            for (int i = 0; i < 2; i++) {
                int idx = tid + i * 256;
                int r = idx >> 2, c8 = (idx & 3) * 8;
                *(uint4*)&vs[r * 40 + c8] = *(const uint4*)&vsrc[r * HEADD + c8];
            }
#pragma unroll
            for (int i = 0; i < 2; i++) {
                int idx = tid + i * 256;
                msp[idx] = g_mask[n0 + (idx >> 2)][tile * 4 + (idx & 3)];
            }
        }
        __syncthreads();

        // ---- MMA1: S = Q @ V^T (f16 m16n8k16, 128x128, K=32 as 2 k-chunks) ----
        float c[16][4];
#pragma unroll
        for (int s = 0; s < 16; s++)
#pragma unroll
            for (int j = 0; j < 4; j++) c[s][j] = 0.f;
#pragma unroll
        for (int kc = 0; kc < 2; kc++) {
            unsigned a[4];
            LDSM_X4(a, qa_base + kc * 32);
#pragma unroll
            for (int subp = 0; subp < 8; subp++) {
                unsigned b[4];
                LDSM_X4(b, vb_base + subp * (16 * 80) + kc * 32);
                mma_f16(c[2 * subp], a[0], a[1], a[2], a[3], b[0], b[1]);
                mma_f16(c[2 * subp + 1], a[0], a[1], a[2], a[3], b[2], b[3]);
            }
        }

        // ---- epilogue: mask + exp -> rowsum; fp16 frags kept in regs + staged to es ----
        unsigned ah0[16], ah1[16];
#pragma unroll
        for (int sub = 0; sub < 16; sub++) {
            int colb = sub * 8 + 2 * tq;
            unsigned w0 = msp[r0 * 4 + (sub >> 2)];
            unsigned w1 = msp[r1 * 4 + (sub >> 2)];
            int sh = colb & 31;
            float e0 = ((w0 >> sh) & 1u) ? __expf(c[sub][0] * SCALE) : 0.f;
            float e1 = ((w0 >> sh) & 2u) ? __expf(c[sub][1] * SCALE) : 0.f;
            float e2 = ((w1 >> sh) & 1u) ? __expf(c[sub][2] * SCALE) : 0.f;
            float e3 = ((w1 >> sh) & 2u) ? __expf(c[sub][3] * SCALE) : 0.f;
            rs0 += e0 + e1;
            rs1 += e2 + e3;
            ah0[sub] = h2u(__floats2half2_rn(e0, e1));
            ah1[sub] = h2u(__floats2half2_rn(e2, e3));
            *(unsigned*)&es[r0 * 136 + colb] = ah0[sub];
            *(unsigned*)&es[r1 * 136 + colb] = ah1[sub];
        }

        // ---- MMA2: O += E @ V (A from regs, B via ldmatrix.trans on vs) ----
#pragma unroll
        for (int kc = 0; kc < 8; kc++) {
            unsigned a0 = ah0[2 * kc], a1 = ah1[2 * kc];
            unsigned a2 = ah0[2 * kc + 1], a3 = ah1[2 * kc + 1];
#pragma unroll
            for (int dsp = 0; dsp < 2; dsp++) {
                unsigned t[4];
                LDSM_X4T(t, vt_base + kc * (16 * 80) + dsp * 32);
                mma_f16(oacc[2 * dsp], a0, a1, a2, a3, t[0], t[1]);
                mma_f16(oacc[2 * dsp + 1], a0, a1, a2, a3, t[2], t[3]);
            }
        }

        // ---- coalesced E tile store: es (smem) -> g_E (row-major) ----
        // 128x128 halves = 2048 uint4 chunks of 8 halves; 256 threads x 8 iters.
        __syncthreads();
        {
            __half* erow = &g_E[head][n0][tile * 128];
#pragma unroll
            for (int i = 0; i < 8; i++) {
                int idx = tid + i * 256;
                int r = idx >> 4, c8 = (idx & 15) * 8;
                *(uint4*)&erow[(size_t)r * NN + c8] = *(const uint4*)&es[r * 136 + c8];
            }
        }
    }

    // rowsum: quad butterfly -> full row sums; normalize O in regs
    rs0 += __shfl_xor_sync(0xffffffffu, rs0, 1);
    rs0 += __shfl_xor_sync(0xffffffffu, rs0, 2);
    rs1 += __shfl_xor_sync(0xffffffffu, rs1, 1);
    rs1 += __shfl_xor_sync(0xffffffffu, rs1, 2);
    float inv0 = 1.0f / rs0;
    float inv1 = 1.0f / rs1;
    if (tq == 0) {
        g_inv[head][n0 + r0] = inv0;
        g_inv[head][n0 + r1] = inv1;
    }
#pragma unroll
    for (int ds = 0; ds < 4; ds++) {
        int col = head * 32 + ds * 8 + 2 * tq;
        *(float2*)&g_obuf[n0 + r0][col] = make_float2(oacc[ds][0] * inv0, oacc[ds][1] * inv0);
        *(float2*)&g_obuf[n0 + r1][col] = make_float2(oacc[ds][2] * inv1, oacc[ds][3] * inv1);
    }
}

// ---------------- pass 2: attn = E * inv (pure streaming) ----------------
__global__ __launch_bounds__(256) void scale_kernel(float* __restrict__ attn) {
    int bid = blockIdx.x;           // one row per block
    int h = bid >> 12;
    int n = bid & (NN - 1);
    float inv = g_inv[h][n];
    const __half2* E = (const __half2*)&g_E[h][n][0];
    float2* dst = (float2*)&attn[((size_t)(h * NN + n)) * NN];
#pragma unroll 4
    for (int i = threadIdx.x; i < NN / 2; i += 256) {
        float2 f = __half22float2(E[i]);
        dst[i] = make_float2(f.x * inv, f.y * inv);
    }
}

// ---------------- launch ----------------
extern "C" void kernel_launch(void* const* d_in, const int* in_sizes, int n_in,
                              void* d_out, int out_size) {
    (void)in_sizes; (void)n_in; (void)out_size;
    const float* x   = (const float*)d_in[0];
    const int*   Adj = (const int*)d_in[1];
    const float* wq  = (const float*)d_in[2];
    const float* bq  = (const float*)d_in[3];
    // wk (d_in[4], d_in[5]) unused: reference has the q@v^T bug
    const float* wv  = (const float*)d_in[6];
    const float* bv  = (const float*)d_in[7];
    const float* wo  = (const float*)d_in[8];
    const float* bo  = (const float*)d_in[9];
    float* out  = (float*)d_out;
    float* attn = out + (size_t)NN * HID;

    cudaFuncSetAttribute(attn_pass1_kernel,
                         cudaFuncAttributeMaxDynamicSharedMemorySize, SMEM_P1);

    pack_mask_kernel<<<(NN * NN) / 256, 256>>>(Adj);

    dim3 pt(16, 16);
    gemm_qv_kernel<<<dim3(NN / 64, HID / 64, 2), pt>>>(x, wq, bq, wv, bv);

    attn_pass1_kernel<<<dim3(32, 8), 256, SMEM_P1>>>();
    scale_kernel<<<NHEADS * NN, 256>>>(attn);

    gemm_o_kernel<<<dim3(NN / 64, HID / 64), pt>>>(wo, bo, out);
}